// round 6
// baseline (speedup 1.0000x reference)
#include <cuda_runtime.h>
#include <cstdint>

#define B_ 16
#define A_ 5
#define C_ 20
#define HF 19
#define WF 19
#define S_ 361           // 19*19
#define N_ 1805          // A_*S_
#define BN 28880         // B_*N_
#define PROB_ELEMS 577600  // B_*N_*C_
#define NW 57            // ceil(1805/32)
#define MROW 64          // padded words per mask row (uint2 x 32)
#define NTILE 1653       // 57*58/2 upper-triangle tiles

__constant__ float c_biases[10] = {1.08f, 1.19f, 3.42f, 4.41f, 6.63f,
                                   11.38f, 9.42f, 5.11f, 16.62f, 10.52f};

// scratch (zero-initialized at module load; padding words of g_mask stay 0
// forever: k_mask only ever writes words 0..56 of each row)
__device__ float g_scores[PROB_ELEMS];                   // [b][c][n]
__device__ float g_x1[BN], g_y1[BN], g_x2[BN], g_y2[BN], g_area[BN];
__device__ unsigned g_mask[(size_t)B_ * N_ * MROW];      // [b][i][word]
__device__ unsigned long long g_order[(size_t)B_ * C_ * N_];

// ---------------------------------------------------------------------------
// K1: decode boxes + scores
// ---------------------------------------------------------------------------
__global__ __launch_bounds__(128) void k_decode(const float* __restrict__ x,
                                                const float* __restrict__ iminfo,
                                                float* __restrict__ out) {
    int t = blockIdx.x * blockDim.x + threadIdx.x;
    if (t >= BN) return;
    int b = t / N_, n = t - b * N_;
    int a = n / S_, s = n - a * S_;
    int hy = s / WF, wx = s - hy * WF;
    const float* p = x + (size_t)b * (125 * S_) + s;

    float tx = p[(2 * a) * S_];
    float ty = p[(2 * a + 1) * S_];
    float tw = p[(10 + 2 * a) * S_];
    float th = p[(11 + 2 * a) * S_];
    float to = p[(20 + a) * S_];

    float sx = 1.0f / (1.0f + expf(-tx));
    float sy = 1.0f / (1.0f + expf(-ty));
    float obj = 1.0f / (1.0f + expf(-to));

    float cf[C_];
    float mx = -1e30f;
#pragma unroll
    for (int c = 0; c < C_; c++) {
        cf[c] = p[(25 + a * C_ + c) * S_];
        mx = fmaxf(mx, cf[c]);
    }
    float sum = 0.0f;
#pragma unroll
    for (int c = 0; c < C_; c++) {
        cf[c] = expf(cf[c] - mx);
        sum += cf[c];
    }
    float osc = obj / sum;

    float imh = iminfo[2 * b + 0];
    float imw = iminfo[2 * b + 1];

    float bx = (sx + (float)wx) / 19.0f * imw;
    float by = (sy + (float)hy) / 19.0f * imh;
    float bw = expf(tw) * c_biases[2 * a] / 19.0f * imw;
    float bh = expf(th) * c_biases[2 * a + 1] / 19.0f * imh;

    reinterpret_cast<float4*>(out + PROB_ELEMS)[t] = make_float4(bx, by, bw, bh);

    float hw = bw * 0.5f, hh = bh * 0.5f;
    g_x1[t] = bx - hw;
    g_x2[t] = bx + hw;
    g_y1[t] = by - hh;
    g_y2[t] = by + hh;
    g_area[t] = bw * bh;

#pragma unroll
    for (int c = 0; c < C_; c++)
        g_scores[((size_t)b * C_ + c) * N_ + n] = cf[c] * osc;
}

// ---------------------------------------------------------------------------
// K2: suppression bitmask, one warp per 32x32 tile, upper triangle + ballot
// ---------------------------------------------------------------------------
__global__ __launch_bounds__(256) void k_mask() {
    int b = blockIdx.x;
    int warp = blockIdx.y * (blockDim.x >> 5) + (threadIdx.x >> 5);
    if (warp >= NTILE) return;
    int lane = threadIdx.x & 31;

    // map warp -> (rb, w) in upper triangle (w >= rb)
    int rb = 0, rem = warp;
    while (rem >= NW - rb) { rem -= NW - rb; rb++; }
    int w = rb + rem;

    int i = rb * 32 + lane;
    int gi = b * N_ + min(i, N_ - 1);
    float ix1 = g_x1[gi], iy1 = g_y1[gi], ix2 = g_x2[gi], iy2 = g_y2[gi];
    float ki = fmaf(0.45f, g_area[gi], 4.5e-10f);

    int jl = w * 32 + lane;
    int gj = b * N_ + min(jl, N_ - 1);
    float cx1 = g_x1[gj], cy1 = g_y1[gj], cx2 = g_x2[gj], cy2 = g_y2[gj];
    float ca = g_area[gj];

    unsigned bits = 0u, tbits = 0u;
    int jbase = w * 32;
#pragma unroll 8
    for (int jj = 0; jj < 32; jj++) {
        float jx1 = __shfl_sync(0xFFFFFFFFu, cx1, jj);
        float jy1 = __shfl_sync(0xFFFFFFFFu, cy1, jj);
        float jx2 = __shfl_sync(0xFFFFFFFFu, cx2, jj);
        float jy2 = __shfl_sync(0xFFFFFFFFu, cy2, jj);
        float ja  = __shfl_sync(0xFFFFFFFFu, ca, jj);
        float iw = fmaxf(fminf(ix2, jx2) - fmaxf(ix1, jx1), 0.0f);
        float ih = fmaxf(fminf(iy2, jy2) - fmaxf(iy1, jy1), 0.0f);
        float inter = iw * ih;
        // inter/(ai+aj-inter+1e-9) > 0.45  <=>  inter*1.45 > 0.45*(ai+aj+1e-9)
        bool pred = (inter * 1.45f > fmaf(0.45f, ja, ki)) && (i != jbase + jj);
        unsigned bal = __ballot_sync(0xFFFFFFFFu, pred);
        bits |= pred ? (1u << jj) : 0u;
        if (lane == jj) tbits = bal;
    }
    if (i < N_) g_mask[(size_t)(b * N_ + i) * MROW + w] = bits;
    if (w != rb && jl < N_) g_mask[(size_t)(b * N_ + jl) * MROW + rb] = tbits;
}

// ---------------------------------------------------------------------------
// K3: bitonic sort (descending) of 2048 packed keys per (b,c)
// key = (score_bits << 32) | (2047 - idx)   -> stable-tie matches argsort
// ---------------------------------------------------------------------------
__global__ __launch_bounds__(1024) void k_sort() {
    __shared__ unsigned long long sm[2048];
    int p = blockIdx.x;           // 0..319 = b*C + c
    int tid = threadIdx.x;
    const float* sc = g_scores + (size_t)p * N_;

#pragma unroll
    for (int q = 0; q < 2; q++) {
        int t = tid + q * 1024;
        unsigned long long key = 0ull;
        if (t < N_)
            key = ((unsigned long long)__float_as_uint(sc[t]) << 32) |
                  (unsigned long long)(2047u - (unsigned)t);
        sm[t] = key;
    }
    __syncthreads();

    for (int k = 2; k <= 2048; k <<= 1) {
        for (int j = k >> 1; j > 0; j >>= 1) {
            int i = ((tid & ~(j - 1)) << 1) | (tid & (j - 1));
            int pi = i | j;
            bool desc = ((i & k) == 0);
            unsigned long long a = sm[i], bb = sm[pi];
            if ((a < bb) == desc) { sm[i] = bb; sm[pi] = a; }
            __syncthreads();
        }
    }

    unsigned long long* op = g_order + (size_t)p * N_;
#pragma unroll
    for (int q = 0; q < 2; q++) {
        int t = tid + q * 1024;
        if (t < N_) op[t] = sm[t];
    }
}

// ---------------------------------------------------------------------------
// helpers: smem release/acquire flag ops
// ---------------------------------------------------------------------------
__device__ __forceinline__ void st_release_cta(unsigned* p, unsigned v) {
    asm volatile("st.release.cta.shared.u32 [%0], %1;"
                 :: "r"((unsigned)__cvta_generic_to_shared(p)), "r"(v) : "memory");
}
__device__ __forceinline__ unsigned ld_acquire_cta(const unsigned* p) {
    unsigned v;
    asm volatile("ld.acquire.cta.shared.u32 %0, [%1];"
                 : "=r"(v) : "r"((unsigned)__cvta_generic_to_shared(p)) : "memory");
    return v;
}

// ---------------------------------------------------------------------------
// K4: greedy NMS, warp-specialized.
// Warps 1..3 (producers): build sup tiles + clamped member indices for all 57
// chunks into smem (flag-released). Warp 0 (consumer): per chunk does keep-bit
// gather, 32-step scalar recurrence, keep update from global rows, store.
// ---------------------------------------------------------------------------
__global__ __launch_bounds__(128, 1) void k_nms(float* __restrict__ out) {
    __shared__ unsigned s_sup[NW * 32];
    __shared__ unsigned s_idx[NW * 32];
    __shared__ unsigned s_flag[NW];

    int p = blockIdx.x;                 // 0..319
    int b = p / C_, c = p - b * C_;
    int tid = threadIdx.x;
    int wid = tid >> 5;
    int lane = tid & 31;

    const unsigned long long* __restrict__ ord = g_order + (size_t)p * N_;
    const unsigned* __restrict__ mbase = g_mask + (size_t)b * N_ * MROW;
    const uint2* __restrict__ mrow2 =
        reinterpret_cast<const uint2*>(g_mask) + (size_t)b * N_ * 32;
    float* __restrict__ op = out + (size_t)b * N_ * C_ + c;

    if (tid < NW) s_flag[tid] = 0u;
    __syncthreads();

    if (wid != 0) {
        // ---------------- producers: tiles wid-1, wid-1+3, ... ----------------
        for (int t = wid - 1; t < NW; t += 3) {
            int rank = t * 32 + lane;
            unsigned long long key = (rank < N_) ? ord[rank] : 0ull;
            unsigned idxr = 2047u - (unsigned)key;          // raw (may be big)
            unsigned idxc = min(idxr, (unsigned)(N_ - 1));  // clamped
            unsigned wqj = idxr >> 5;                       // 63 for invalid -> pad word
            unsigned bmask = 1u << (idxr & 31u);

            s_idx[t * 32 + lane] = idxc;

            // member i's row word at this lane's column
            unsigned mysup = 0u;
#pragma unroll
            for (int i = 0; i < 32; i++) {
                unsigned idxi = __shfl_sync(0xFFFFFFFFu, idxc, i);
                unsigned q = mbase[idxi * 64u + wqj];
                unsigned bal = __ballot_sync(0xFFFFFFFFu, (q & bmask) != 0u);
                if (lane == i) mysup = bal & (0xFFFFFFFEu << i);
            }
            s_sup[t * 32 + lane] = mysup;
            __syncwarp();
            if (lane == 0) st_release_cta(&s_flag[t], 1u);
        }
        return;
    }

    // ---------------- consumer: warp 0 ----------------
    unsigned keepX = 0xFFFFFFFFu, keepY = 0xFFFFFFFFu;
    unsigned long long key = ord[lane];          // chunk 0 ranks all < N_

    for (int ch = 0; ch < NW; ch++) {
        int rank = ch * 32 + lane;
        unsigned valid = (rank < N_) ? 1u : 0u;
        unsigned idxj = 2047u - (unsigned)key;
        unsigned wqj = idxj >> 5;
        unsigned bmask = 1u << (idxj & 31u);
        float scorej = __uint_as_float((unsigned)(key >> 32));

        // next chunk's key (off-chain)
        int nrank = rank + 32;
        unsigned long long nkey = (nrank < N_) ? ord[nrank] : 0ull;

        // wait for this chunk's tile (producers run well ahead)
        while (ld_acquire_cta(&s_flag[ch]) == 0u) { }

        // issue row loads + read sup words (broadcast LDS, off-chain)
        uint2 m[32];
        unsigned sup[32];
#pragma unroll
        for (int i = 0; i < 32; i++) {
            unsigned idxi = s_idx[ch * 32 + i];
            m[i] = mrow2[idxi * 32u + lane];
            sup[i] = s_sup[ch * 32 + i];
        }

        // gather this chunk's keep bits -> uniform 'alive'
        unsigned vx = __shfl_sync(0xFFFFFFFFu, keepX, wqj >> 1);
        unsigned vy = __shfl_sync(0xFFFFFFFFu, keepY, wqj >> 1);
        unsigned wv = (wqj & 1u) ? vy : vx;
        unsigned alive =
            __ballot_sync(0xFFFFFFFFu, (wv & bmask) != 0u && valid);

        // serial greedy recurrence (bit i final at step i; 1 SHF + 1 LOP3/step)
#pragma unroll
        for (int i = 0; i < 32; i++) {
            unsigned msk = (unsigned)((int)(alive << (31 - i)) >> 31);
            alive &= ~(sup[i] & msk);
        }

        // keep update from register-resident rows
        unsigned cmbx = 0u, cmby = 0u;
#pragma unroll
        for (int i = 0; i < 32; i++) {
            unsigned msk = (unsigned)((int)(alive << (31 - i)) >> 31);
            cmbx |= m[i].x & msk;
            cmby |= m[i].y & msk;
        }
        keepX &= ~cmbx;
        keepY &= ~cmby;

        // per-lane predicated store
        float val = ((alive >> lane) & 1u) ? scorej : 0.0f;
        float* addr = op + (size_t)idxj * C_;
        asm volatile(
            "{ .reg .pred p; setp.ne.u32 p, %0, 0;\n"
            "  @p st.global.f32 [%1], %2; }"
            :: "r"(valid), "l"(addr), "f"(val) : "memory");

        key = nkey;
    }
}

// ---------------------------------------------------------------------------
extern "C" void kernel_launch(void* const* d_in, const int* in_sizes, int n_in,
                              void* d_out, int out_size) {
    const float* x = (const float*)d_in[0];
    const float* iminfo = (const float*)d_in[1];
    float* out = (float*)d_out;

    k_decode<<<(BN + 127) / 128, 128>>>(x, iminfo, out);

    dim3 gm(B_, (NTILE + 7) / 8);
    k_mask<<<gm, 256>>>();

    k_sort<<<B_ * C_, 1024>>>();

    k_nms<<<B_ * C_, 128>>>(out);
}

// round 7
// speedup vs baseline: 1.2063x; 1.2063x over previous
#include <cuda_runtime.h>
#include <cstdint>

#define B_ 16
#define A_ 5
#define C_ 20
#define HF 19
#define WF 19
#define S_ 361           // 19*19
#define N_ 1805          // A_*S_
#define BN 28880         // B_*N_
#define PROB_ELEMS 577600  // B_*N_*C_
#define NW 57            // ceil(1805/32)
#define MROW 64          // padded words per mask row (uint2 x 32)
#define NTILE 1653       // 57*58/2 upper-triangle tiles

__constant__ float c_biases[10] = {1.08f, 1.19f, 3.42f, 4.41f, 6.63f,
                                   11.38f, 9.42f, 5.11f, 16.62f, 10.52f};

// scratch (zero-initialized; g_mask padding words 0..: k_mask only writes
// words 0..56 of each 64-word row, so word 57..63 stay 0 forever)
__device__ float g_scores[PROB_ELEMS];                   // [b][c][n]
__device__ float g_x1[BN], g_y1[BN], g_x2[BN], g_y2[BN], g_area[BN];
__device__ unsigned g_mask[(size_t)B_ * N_ * MROW];      // [b][i][word]
__device__ unsigned long long g_order[(size_t)B_ * C_ * N_];
// per (p,chunk): words 0..31 = clamped member indices, 32..63 = sup words
__device__ unsigned g_supidx[(size_t)B_ * C_ * NW * 64];

// ---------------------------------------------------------------------------
// K1: decode boxes + scores
// ---------------------------------------------------------------------------
__global__ __launch_bounds__(128) void k_decode(const float* __restrict__ x,
                                                const float* __restrict__ iminfo,
                                                float* __restrict__ out) {
    int t = blockIdx.x * blockDim.x + threadIdx.x;
    if (t >= BN) return;
    int b = t / N_, n = t - b * N_;
    int a = n / S_, s = n - a * S_;
    int hy = s / WF, wx = s - hy * WF;
    const float* p = x + (size_t)b * (125 * S_) + s;

    float tx = p[(2 * a) * S_];
    float ty = p[(2 * a + 1) * S_];
    float tw = p[(10 + 2 * a) * S_];
    float th = p[(11 + 2 * a) * S_];
    float to = p[(20 + a) * S_];

    float sx = 1.0f / (1.0f + expf(-tx));
    float sy = 1.0f / (1.0f + expf(-ty));
    float obj = 1.0f / (1.0f + expf(-to));

    float cf[C_];
    float mx = -1e30f;
#pragma unroll
    for (int c = 0; c < C_; c++) {
        cf[c] = p[(25 + a * C_ + c) * S_];
        mx = fmaxf(mx, cf[c]);
    }
    float sum = 0.0f;
#pragma unroll
    for (int c = 0; c < C_; c++) {
        cf[c] = expf(cf[c] - mx);
        sum += cf[c];
    }
    float osc = obj / sum;

    float imh = iminfo[2 * b + 0];
    float imw = iminfo[2 * b + 1];

    float bx = (sx + (float)wx) / 19.0f * imw;
    float by = (sy + (float)hy) / 19.0f * imh;
    float bw = expf(tw) * c_biases[2 * a] / 19.0f * imw;
    float bh = expf(th) * c_biases[2 * a + 1] / 19.0f * imh;

    reinterpret_cast<float4*>(out + PROB_ELEMS)[t] = make_float4(bx, by, bw, bh);

    float hw = bw * 0.5f, hh = bh * 0.5f;
    g_x1[t] = bx - hw;
    g_x2[t] = bx + hw;
    g_y1[t] = by - hh;
    g_y2[t] = by + hh;
    g_area[t] = bw * bh;

#pragma unroll
    for (int c = 0; c < C_; c++)
        g_scores[((size_t)b * C_ + c) * N_ + n] = cf[c] * osc;
}

// ---------------------------------------------------------------------------
// K2: suppression bitmask, one warp per 32x32 tile, upper triangle + ballot
// ---------------------------------------------------------------------------
__global__ __launch_bounds__(256) void k_mask() {
    int b = blockIdx.x;
    int warp = blockIdx.y * (blockDim.x >> 5) + (threadIdx.x >> 5);
    if (warp >= NTILE) return;
    int lane = threadIdx.x & 31;

    // map warp -> (rb, w) in upper triangle (w >= rb)
    int rb = 0, rem = warp;
    while (rem >= NW - rb) { rem -= NW - rb; rb++; }
    int w = rb + rem;

    int i = rb * 32 + lane;
    int gi = b * N_ + min(i, N_ - 1);
    float ix1 = g_x1[gi], iy1 = g_y1[gi], ix2 = g_x2[gi], iy2 = g_y2[gi];
    float ki = fmaf(0.45f, g_area[gi], 4.5e-10f);

    int jl = w * 32 + lane;
    int gj = b * N_ + min(jl, N_ - 1);
    float cx1 = g_x1[gj], cy1 = g_y1[gj], cx2 = g_x2[gj], cy2 = g_y2[gj];
    float ca = g_area[gj];

    unsigned bits = 0u, tbits = 0u;
    int jbase = w * 32;
#pragma unroll 8
    for (int jj = 0; jj < 32; jj++) {
        float jx1 = __shfl_sync(0xFFFFFFFFu, cx1, jj);
        float jy1 = __shfl_sync(0xFFFFFFFFu, cy1, jj);
        float jx2 = __shfl_sync(0xFFFFFFFFu, cx2, jj);
        float jy2 = __shfl_sync(0xFFFFFFFFu, cy2, jj);
        float ja  = __shfl_sync(0xFFFFFFFFu, ca, jj);
        float iw = fmaxf(fminf(ix2, jx2) - fmaxf(ix1, jx1), 0.0f);
        float ih = fmaxf(fminf(iy2, jy2) - fmaxf(iy1, jy1), 0.0f);
        float inter = iw * ih;
        // inter/(ai+aj-inter+1e-9) > 0.45  <=>  inter*1.45 > 0.45*(ai+aj+1e-9)
        bool pred = (inter * 1.45f > fmaf(0.45f, ja, ki)) && (i != jbase + jj);
        unsigned bal = __ballot_sync(0xFFFFFFFFu, pred);
        bits |= pred ? (1u << jj) : 0u;
        if (lane == jj) tbits = bal;
    }
    if (i < N_) g_mask[(size_t)(b * N_ + i) * MROW + w] = bits;
    if (w != rb && jl < N_) g_mask[(size_t)(b * N_ + jl) * MROW + rb] = tbits;
}

// ---------------------------------------------------------------------------
// K3: bitonic sort (descending) of 2048 packed keys per (b,c)
// key = (score_bits << 32) | (2047 - idx)   -> stable-tie matches argsort
// ---------------------------------------------------------------------------
__global__ __launch_bounds__(1024) void k_sort() {
    __shared__ unsigned long long sm[2048];
    int p = blockIdx.x;           // 0..319 = b*C + c
    int tid = threadIdx.x;
    const float* sc = g_scores + (size_t)p * N_;

#pragma unroll
    for (int q = 0; q < 2; q++) {
        int t = tid + q * 1024;
        unsigned long long key = 0ull;
        if (t < N_)
            key = ((unsigned long long)__float_as_uint(sc[t]) << 32) |
                  (unsigned long long)(2047u - (unsigned)t);
        sm[t] = key;
    }
    __syncthreads();

    for (int k = 2; k <= 2048; k <<= 1) {
        for (int j = k >> 1; j > 0; j >>= 1) {
            int i = ((tid & ~(j - 1)) << 1) | (tid & (j - 1));
            int pi = i | j;
            bool desc = ((i & k) == 0);
            unsigned long long a = sm[i], bb = sm[pi];
            if ((a < bb) == desc) { sm[i] = bb; sm[pi] = a; }
            __syncthreads();
        }
    }

    unsigned long long* op = g_order + (size_t)p * N_;
#pragma unroll
    for (int q = 0; q < 2; q++) {
        int t = tid + q * 1024;
        if (t < N_) op[t] = sm[t];
    }
}

// ---------------------------------------------------------------------------
// K3b: precompute per-(p,chunk) member indices + sup words.
// One warp per (p, chunk): all the SHFL/ballot-heavy work, fully parallel
// (18240 warps), so the serial NMS kernel never does it.
// ---------------------------------------------------------------------------
__global__ __launch_bounds__(128) void k_sup() {
    int p = blockIdx.x;                       // 0..319
    int t = blockIdx.y * 4 + (threadIdx.x >> 5);
    if (t >= NW) return;
    int lane = threadIdx.x & 31;
    int b = p / C_;

    const unsigned long long* __restrict__ ord = g_order + (size_t)p * N_;
    const unsigned* __restrict__ mbase = g_mask + (size_t)b * N_ * MROW;

    int rank = t * 32 + lane;
    unsigned long long key = (rank < N_) ? ord[rank] : 0ull;
    unsigned idxr = 2047u - (unsigned)key;           // 2047 for invalid
    unsigned idxc = min(idxr, (unsigned)(N_ - 1));
    unsigned wq = idxr >> 5;                         // 63 for invalid -> pad word (0)
    unsigned bmask = 1u << (idxr & 31u);

    unsigned mysup = 0u;
#pragma unroll
    for (int i = 0; i < 32; i++) {
        unsigned idxi = __shfl_sync(0xFFFFFFFFu, idxc, i);
        unsigned q = mbase[(size_t)idxi * 64u + wq];
        unsigned bal = __ballot_sync(0xFFFFFFFFu, (q & bmask) != 0u);
        if (lane == i) mysup = bal & (0xFFFFFFFEu << i);
    }

    unsigned* dst = g_supidx + ((size_t)p * NW + t) * 64u;
    dst[lane] = idxc;
    dst[32 + lane] = mysup;
}

// ---------------------------------------------------------------------------
// K4: greedy NMS. Block = 128 threads: all 4 warps stage this problem's
// sup/idx table (14.6 KB) into smem, then warp 0 alone runs the serial scan.
// Warp 0's chunk body: 16 broadcast LDS.128 + 32 LDG.64 rows + one gather
// (2 SHFL + 1 ballot) + 32-step recurrence + OR-tree + 1 predicated STG.
// ---------------------------------------------------------------------------
__global__ __launch_bounds__(128, 1) void k_nms(float* __restrict__ out) {
    __shared__ unsigned s_tab[NW * 64];

    int p = blockIdx.x;                 // 0..319
    int b = p / C_, c = p - b * C_;
    int tid = threadIdx.x;
    int lane = tid & 31;

    // cooperative staging: 912 uint4
    {
        const uint4* g4 = reinterpret_cast<const uint4*>(
            g_supidx + (size_t)p * NW * 64u);
        uint4* s4w = reinterpret_cast<uint4*>(s_tab);
#pragma unroll
        for (int k = 0; k < 8; k++) {
            int t = tid + k * 128;
            if (t < NW * 16) s4w[t] = g4[t];
        }
    }
    __syncthreads();
    if (tid >= 32) return;

    const unsigned long long* __restrict__ ord = g_order + (size_t)p * N_;
    const uint2* __restrict__ mrow2 =
        reinterpret_cast<const uint2*>(g_mask) + (size_t)b * N_ * 32;
    const uint4* __restrict__ s4 = reinterpret_cast<const uint4*>(s_tab);
    float* __restrict__ op = out + (size_t)b * N_ * C_ + c;

    unsigned keepX = 0xFFFFFFFFu, keepY = 0xFFFFFFFFu;
    unsigned long long key = ord[lane];

    for (int ch = 0; ch < NW; ch++) {
        int rank = ch * 32 + lane;
        unsigned valid = (rank < N_) ? 1u : 0u;
        unsigned idxj = 2047u - (unsigned)key;
        unsigned wqj = idxj >> 5;
        unsigned bmask = 1u << (idxj & 31u);
        float scorej = __uint_as_float((unsigned)(key >> 32));

        // next chunk's key (off-chain)
        int nrank = rank + 32;
        unsigned long long nkey = (nrank < N_) ? ord[nrank] : 0ull;

        // member rows: indices via broadcast LDS.128, loads issued immediately
        uint2 m[32];
#pragma unroll
        for (int k = 0; k < 8; k++) {
            uint4 a = s4[ch * 16 + k];
            m[4 * k + 0] = mrow2[a.x * 32u + lane];
            m[4 * k + 1] = mrow2[a.y * 32u + lane];
            m[4 * k + 2] = mrow2[a.z * 32u + lane];
            m[4 * k + 3] = mrow2[a.w * 32u + lane];
        }
        // sup words via broadcast LDS.128
        unsigned sup[32];
#pragma unroll
        for (int k = 0; k < 8; k++) {
            uint4 a = s4[ch * 16 + 8 + k];
            sup[4 * k + 0] = a.x;
            sup[4 * k + 1] = a.y;
            sup[4 * k + 2] = a.z;
            sup[4 * k + 3] = a.w;
        }

        // gather this chunk's keep bits -> uniform 'alive'
        unsigned vx = __shfl_sync(0xFFFFFFFFu, keepX, wqj >> 1);
        unsigned vy = __shfl_sync(0xFFFFFFFFu, keepY, wqj >> 1);
        unsigned wv = (wqj & 1u) ? vy : vx;
        unsigned alive =
            __ballot_sync(0xFFFFFFFFu, (wv & bmask) != 0u && valid);

        // serial greedy recurrence (bit i of alive is final at step i)
#pragma unroll
        for (int i = 0; i < 32; i++) {
            unsigned msk = (unsigned)((int)(alive << (31 - i)) >> 31);
            alive &= ~(sup[i] & msk);
        }

        // keep update: OR-tree of kept members' rows (4 partials)
        unsigned cx0 = 0u, cx1 = 0u, cy0 = 0u, cy1 = 0u;
#pragma unroll
        for (int i = 0; i < 32; i += 2) {
            unsigned msk0 = (unsigned)((int)(alive << (31 - i)) >> 31);
            unsigned msk1 = (unsigned)((int)(alive << (30 - i)) >> 31);
            cx0 |= m[i].x & msk0;
            cy0 |= m[i].y & msk0;
            cx1 |= m[i + 1].x & msk1;
            cy1 |= m[i + 1].y & msk1;
        }
        keepX &= ~(cx0 | cx1);
        keepY &= ~(cy0 | cy1);

        // per-lane predicated store
        float val = ((alive >> lane) & 1u) ? scorej : 0.0f;
        float* addr = op + (size_t)idxj * C_;
        asm volatile(
            "{ .reg .pred p; setp.ne.u32 p, %0, 0;\n"
            "  @p st.global.f32 [%1], %2; }"
            :: "r"(valid), "l"(addr), "f"(val) : "memory");

        key = nkey;
    }
}

// ---------------------------------------------------------------------------
extern "C" void kernel_launch(void* const* d_in, const int* in_sizes, int n_in,
                              void* d_out, int out_size) {
    const float* x = (const float*)d_in[0];
    const float* iminfo = (const float*)d_in[1];
    float* out = (float*)d_out;

    k_decode<<<(BN + 127) / 128, 128>>>(x, iminfo, out);

    dim3 gm(B_, (NTILE + 7) / 8);
    k_mask<<<gm, 256>>>();

    k_sort<<<B_ * C_, 1024>>>();

    dim3 gs(B_ * C_, (NW + 3) / 4);
    k_sup<<<gs, 128>>>();

    k_nms<<<B_ * C_, 128>>>(out);
}